// round 8
// baseline (speedup 1.0000x reference)
#include <cuda_runtime.h>
#include <math_constants.h>
#include <cstdint>

#define BATCH   4
#define N_UP    16384
#define N_DOWN  4096
#define C_UP    384
#define C_DOWN  512
#define C_OUT   512
#define KNN     3
#define EPSW    1e-8f

#define M_UP   (BATCH * N_UP)     // 65536
#define M_DN   (BATCH * N_DOWN)   // 16384

// ---------------- scratch (__device__ globals; no allocs allowed) ----------
__device__ float g_down_f[M_DN * C_OUT];                 // 32 MB fp32
__device__ int   g_idx[M_UP * KNN];
__device__ float g_w[M_UP * KNN];

__device__ unsigned short g_Ah_up[(size_t)M_UP * C_UP];
__device__ unsigned short g_Al_up[(size_t)M_UP * C_UP];
__device__ unsigned short g_Wh_up[(size_t)C_OUT * C_UP];
__device__ unsigned short g_Wl_up[(size_t)C_OUT * C_UP];
__device__ unsigned short g_Ah_dn[(size_t)M_DN * C_DOWN];
__device__ unsigned short g_Al_dn[(size_t)M_DN * C_DOWN];
__device__ unsigned short g_Wh_dn[(size_t)C_OUT * C_DOWN];
__device__ unsigned short g_Wl_dn[(size_t)C_OUT * C_DOWN];

// ---------------- helpers ---------------------------------------------------
static __device__ __forceinline__ uint32_t smem_u32(const void* p) {
    uint32_t a;
    asm("{ .reg .u64 t; cvta.to.shared.u64 t, %1; cvt.u32.u64 %0, t; }"
        : "=r"(a) : "l"(p));
    return a;
}
static __device__ __forceinline__ unsigned short f2bf(float f) {
    unsigned short u;
    asm("cvt.rn.bf16.f32 %0, %1;" : "=h"(u) : "f"(f));
    return u;
}
static __device__ __forceinline__ float bf2f(unsigned short u) {
    return __uint_as_float(((uint32_t)u) << 16);
}
static __device__ __forceinline__ void cp16(uint32_t dst, const void* src) {
    asm volatile("cp.async.cg.shared.global [%0], [%1], 16;"
                 :: "r"(dst), "l"(src) : "memory");
}
static __device__ __forceinline__ void cp_commit() {
    asm volatile("cp.async.commit_group;" ::: "memory");
}
static __device__ __forceinline__ void cp_wait2() {
    asm volatile("cp.async.wait_group 2;" ::: "memory");
}
static __device__ __forceinline__ void ldmx4(uint32_t& r0, uint32_t& r1,
                                             uint32_t& r2, uint32_t& r3,
                                             uint32_t addr) {
    asm volatile("ldmatrix.sync.aligned.m8n8.x4.shared.b16 {%0,%1,%2,%3}, [%4];"
                 : "=r"(r0), "=r"(r1), "=r"(r2), "=r"(r3) : "r"(addr));
}
static __device__ __forceinline__ void mma16816(float* c, const uint32_t* a,
                                                uint32_t b0, uint32_t b1) {
    asm volatile(
        "mma.sync.aligned.m16n8k16.row.col.f32.bf16.bf16.f32 "
        "{%0,%1,%2,%3}, {%4,%5,%6,%7}, {%8,%9}, {%0,%1,%2,%3};"
        : "+f"(c[0]), "+f"(c[1]), "+f"(c[2]), "+f"(c[3])
        : "r"(a[0]), "r"(a[1]), "r"(a[2]), "r"(a[3]), "r"(b0), "r"(b1));
}

// ---------------- hi/lo bf16 split -----------------------------------------
__global__ __launch_bounds__(256) void conv_hilo(
    const float4* __restrict__ x, ushort4* __restrict__ h4,
    ushort4* __restrict__ l4, int n4)
{
    int i = blockIdx.x * 256 + threadIdx.x;
    if (i >= n4) return;
    float4 v = x[i];
    ushort4 h, l;
    h.x = f2bf(v.x); l.x = f2bf(v.x - bf2f(h.x));
    h.y = f2bf(v.y); l.y = f2bf(v.y - bf2f(h.y));
    h.z = f2bf(v.z); l.z = f2bf(v.z - bf2f(h.z));
    h.w = f2bf(v.w); l.w = f2bf(v.w - bf2f(h.w));
    h4[i] = h; l4[i] = l;
}

// ---------------------------------------------------------------------------
// bf16 hi/lo GEMM via mma.sync: out[m,n] = sum_k A[m,k]*Wt[n,k] + bias[n]
// (+ KNN interpolation when FUSED). Effective K' = 3K via segments:
//   seg0: Ah*Bh   seg1: Ah*Bl   seg2: Al*Bh
// CTA 128x128, BK=32 bf16, 4-stage cp.async ring, 16 warps (512 thr),
// warp tile 64x16 (4 warps/SMSP for latency hiding), m16n8k16.
// ---------------------------------------------------------------------------
#define SM_STAGE 20480            // (128 rows * 80B) * 2 (A+B)
template<int K, bool FUSED>
__global__ __launch_bounds__(512) void gemm_bf16(
    const unsigned short* __restrict__ Ah, const unsigned short* __restrict__ Al,
    const unsigned short* __restrict__ Bh, const unsigned short* __restrict__ Bl,
    const float* __restrict__ bias, float* __restrict__ outp)
{
    constexpr int SEGC = K / 32;
    constexpr int NC = 3 * SEGC;
    extern __shared__ __align__(16) char smt[];
    const uint32_t sbase = smem_u32(smt);

    const int tid = threadIdx.x;
    const int lane = tid & 31;
    const int wid = tid >> 5;
    const int wm = wid >> 3;        // 0..1 -> m offset wm*64
    const int wn = wid & 7;         // 0..7 -> n offset wn*16
    const int m0 = blockIdx.y * 128;
    const int n0 = blockIdx.x * 128;

    // cp.async: 1024 16B slots per chunk (A 512 + B 512), 2 per thread
    const int s0 = tid;             // slot ids: s0, s0 + 512

    // ldmatrix per-lane offsets
    const int lq = lane >> 3, l7 = lane & 7;
    const int aRow = (lq & 1) * 8 + l7, aK = (lq >> 1) * 8;
    const int bRow = (lq >> 1) * 8 + l7, bK = (lq & 1) * 8;

    float acc[4][2][4];
#pragma unroll
    for (int i = 0; i < 4; i++)
#pragma unroll
        for (int j = 0; j < 2; j++)
#pragma unroll
            for (int r = 0; r < 4; r++) acc[i][j][r] = 0.0f;

    auto issue = [&](int c) {
        if (c < NC) {
            const int seg = c / SEGC;
            const int kk = (c - seg * SEGC) * 32;
            const unsigned short* As = (seg < 2) ? Ah : Al;
            const unsigned short* Bs = (seg == 1) ? Bl : Bh;
#pragma unroll
            for (int ss = 0; ss < 2; ss++) {
                const int s = s0 + ss * 512;
                const bool isB = s >= 512;
                const int r = (s & 511) >> 2;
                const int q = s & 3;
                const unsigned short* src = (isB ? (Bs + (size_t)(n0 + r) * K)
                                                 : (As + (size_t)(m0 + r) * K))
                                            + kk + q * 8;
                uint32_t dst = sbase + (c & 3) * SM_STAGE + (isB ? 10240 : 0)
                             + r * 80 + q * 16;
                cp16(dst, src);
            }
        }
        cp_commit();
    };

    issue(0); issue(1); issue(2);

    for (int c = 0; c < NC; c++) {
        cp_wait2();
        __syncthreads();
        issue(c + 3);                 // overwrites stage (c-1)&3: safe past sync

        const uint32_t sA = sbase + (c & 3) * SM_STAGE;
        const uint32_t sB = sA + 10240;
#pragma unroll
        for (int ks = 0; ks < 2; ks++) {
            uint32_t a[4][4];
#pragma unroll
            for (int i = 0; i < 4; i++) {
                uint32_t addr = sA + (uint32_t)(wm * 64 + i * 16 + aRow) * 80
                              + (uint32_t)(ks * 16 + aK) * 2;
                ldmx4(a[i][0], a[i][1], a[i][2], a[i][3], addr);
            }
            uint32_t b[2][2];
            {
                uint32_t addr = sB + (uint32_t)(wn * 16 + bRow) * 80
                              + (uint32_t)(ks * 16 + bK) * 2;
                ldmx4(b[0][0], b[0][1], b[1][0], b[1][1], addr);
            }
#pragma unroll
            for (int i = 0; i < 4; i++)
#pragma unroll
                for (int j = 0; j < 2; j++)
                    mma16816(acc[i][j], a[i], b[j][0], b[j][1]);
        }
    }

    // ---------------- epilogue ----------------
    float* obase = FUSED ? outp : g_down_f;
#pragma unroll
    for (int i = 0; i < 4; i++) {
        const int r0 = m0 + wm * 64 + i * 16 + (lane >> 2);
        const int r1 = r0 + 8;
        const float* df0 = nullptr; const float* df1 = nullptr;
        int i00=0,i01=0,i02=0, i10=0,i11=0,i12=0;
        float w00=0,w01=0,w02=0, w10=0,w11=0,w12=0;
        if (FUSED) {
            df0 = g_down_f + (size_t)(r0 >> 14) * N_DOWN * C_OUT;
            df1 = g_down_f + (size_t)(r1 >> 14) * N_DOWN * C_OUT;
            int ib0 = r0 * KNN, ib1 = r1 * KNN;
            i00 = g_idx[ib0]; i01 = g_idx[ib0+1]; i02 = g_idx[ib0+2];
            w00 = g_w[ib0];   w01 = g_w[ib0+1];   w02 = g_w[ib0+2];
            i10 = g_idx[ib1]; i11 = g_idx[ib1+1]; i12 = g_idx[ib1+2];
            w10 = g_w[ib1];   w11 = g_w[ib1+1];   w12 = g_w[ib1+2];
        }
#pragma unroll
        for (int j = 0; j < 2; j++) {
            const int n = n0 + wn * 16 + j * 8 + (lane & 3) * 2;
            const float2 bi = *(const float2*)(bias + n);
            float2 o0, o1;
            o0.x = acc[i][j][0] + bi.x;  o0.y = acc[i][j][1] + bi.y;
            o1.x = acc[i][j][2] + bi.x;  o1.y = acc[i][j][3] + bi.y;
            if (FUSED) {
                float2 a0 = *(const float2*)(df0 + (size_t)i00 * C_OUT + n);
                float2 a1 = *(const float2*)(df0 + (size_t)i01 * C_OUT + n);
                float2 a2 = *(const float2*)(df0 + (size_t)i02 * C_OUT + n);
                o0.x += w00 * a0.x + w01 * a1.x + w02 * a2.x;
                o0.y += w00 * a0.y + w01 * a1.y + w02 * a2.y;
                float2 c0 = *(const float2*)(df1 + (size_t)i10 * C_OUT + n);
                float2 c1 = *(const float2*)(df1 + (size_t)i11 * C_OUT + n);
                float2 c2 = *(const float2*)(df1 + (size_t)i12 * C_OUT + n);
                o1.x += w10 * c0.x + w11 * c1.x + w12 * c2.x;
                o1.y += w10 * c0.y + w11 * c1.y + w12 * c2.y;
            }
            *(float2*)(obase + (size_t)r0 * C_OUT + n) = o0;
            *(float2*)(obase + (size_t)r1 * C_OUT + n) = o1;
        }
    }
}

// ---------------------------------------------------------------------------
// KNN: rank by t = d2 - 2*dot; strict-< insertion for stability.
// ---------------------------------------------------------------------------
__global__ __launch_bounds__(256) void knn_kernel(
    const float* __restrict__ up_points,
    const float* __restrict__ down_points)
{
    __shared__ float4 sp[2048];

    const int b = blockIdx.y;
    const int n = blockIdx.x * 256 + threadIdx.x;

    const float* up = up_points + (size_t)(b * N_UP + n) * 3;
    const float ux = up[0], uy = up[1], uz = up[2];
    const float u2 = ux * ux + uy * uy + uz * uz;
    const float a0 = -2.0f * ux, a1 = -2.0f * uy, a2 = -2.0f * uz;

    float bd0 = CUDART_INF_F, bd1 = CUDART_INF_F, bd2 = CUDART_INF_F;
    int   bi0 = 0, bi1 = 0, bi2 = 0;

    for (int phase = 0; phase < 2; phase++) {
        const int mbase = phase * 2048;
        __syncthreads();
        for (int i = threadIdx.x; i < 2048; i += 256) {
            const float* dp = down_points + (size_t)(b * N_DOWN + mbase + i) * 3;
            float x = dp[0], y = dp[1], z = dp[2];
            sp[i] = make_float4(x, y, z, x * x + y * y + z * z);
        }
        __syncthreads();

        for (int m = 0; m < 2048; m += 8) {
            float t[8];
#pragma unroll
            for (int j = 0; j < 8; j++) {
                float4 p = sp[m + j];
                t[j] = fmaf(a0, p.x, fmaf(a1, p.y, fmaf(a2, p.z, p.w)));
            }
            float mn = fminf(fminf(fminf(t[0], t[1]), fminf(t[2], t[3])),
                             fminf(fminf(t[4], t[5]), fminf(t[6], t[7])));
            if (mn < bd2) {
#pragma unroll
                for (int j = 0; j < 8; j++) {
                    float d = t[j];
                    if (d < bd2) {
                        int mi = mbase + m + j;
                        if (d < bd1) {
                            bd2 = bd1; bi2 = bi1;
                            if (d < bd0) { bd1 = bd0; bi1 = bi0; bd0 = d; bi0 = mi; }
                            else          { bd1 = d;  bi1 = mi; }
                        } else {
                            bd2 = d; bi2 = mi;
                        }
                    }
                }
            }
        }
    }

    float d0 = bd0 + u2, d1 = bd1 + u2, d2 = bd2 + u2;
    float w0 = 1.0f / (d0 + EPSW);
    float w1 = 1.0f / (d1 + EPSW);
    float w2 = 1.0f / (d2 + EPSW);
    float inv = 1.0f / (w0 + w1 + w2);

    const int base = (b * N_UP + n) * KNN;
    g_idx[base + 0] = bi0; g_idx[base + 1] = bi1; g_idx[base + 2] = bi2;
    g_w[base + 0] = w0 * inv; g_w[base + 1] = w1 * inv; g_w[base + 2] = w2 * inv;
}

// ---------------------------------------------------------------------------
extern "C" void kernel_launch(void* const* d_in, const int* in_sizes, int n_in,
                              void* d_out, int out_size) {
    (void)in_sizes; (void)n_in; (void)out_size;
    const float* up_points     = (const float*)d_in[0];
    const float* up_features   = (const float*)d_in[1];
    const float* down_points   = (const float*)d_in[2];
    const float* down_features = (const float*)d_in[3];
    const float* W_up          = (const float*)d_in[4];
    const float* b_up          = (const float*)d_in[5];
    const float* W_down        = (const float*)d_in[6];
    const float* b_down        = (const float*)d_in[7];
    float* out = (float*)d_out;

    void *pAhU, *pAlU, *pWhU, *pWlU, *pAhD, *pAlD, *pWhD, *pWlD;
    cudaGetSymbolAddress(&pAhU, g_Ah_up);
    cudaGetSymbolAddress(&pAlU, g_Al_up);
    cudaGetSymbolAddress(&pWhU, g_Wh_up);
    cudaGetSymbolAddress(&pWlU, g_Wl_up);
    cudaGetSymbolAddress(&pAhD, g_Ah_dn);
    cudaGetSymbolAddress(&pAlD, g_Al_dn);
    cudaGetSymbolAddress(&pWhD, g_Wh_dn);
    cudaGetSymbolAddress(&pWlD, g_Wl_dn);

    cudaFuncSetAttribute(gemm_bf16<C_DOWN, false>,
                         cudaFuncAttributeMaxDynamicSharedMemorySize, 4 * SM_STAGE);
    cudaFuncSetAttribute(gemm_bf16<C_UP, true>,
                         cudaFuncAttributeMaxDynamicSharedMemorySize, 4 * SM_STAGE);

    // hi/lo splits
    {
        int n4 = M_UP * C_UP / 4;
        conv_hilo<<<(n4 + 255) / 256, 256>>>((const float4*)up_features,
                                             (ushort4*)pAhU, (ushort4*)pAlU, n4);
    }
    {
        int n4 = C_OUT * C_UP / 4;
        conv_hilo<<<(n4 + 255) / 256, 256>>>((const float4*)W_up,
                                             (ushort4*)pWhU, (ushort4*)pWlU, n4);
    }
    {
        int n4 = M_DN * C_DOWN / 4;
        conv_hilo<<<(n4 + 255) / 256, 256>>>((const float4*)down_features,
                                             (ushort4*)pAhD, (ushort4*)pAlD, n4);
    }
    {
        int n4 = C_OUT * C_DOWN / 4;
        conv_hilo<<<(n4 + 255) / 256, 256>>>((const float4*)W_down,
                                             (ushort4*)pWhD, (ushort4*)pWlD, n4);
    }

    dim3 gk(N_UP / 256, BATCH);
    knn_kernel<<<gk, 256>>>(up_points, down_points);

    dim3 g1(C_OUT / 128, M_DN / 128);   // (4, 128)
    gemm_bf16<C_DOWN, false><<<g1, 512, 4 * SM_STAGE>>>(
        (const unsigned short*)pAhD, (const unsigned short*)pAlD,
        (const unsigned short*)pWhD, (const unsigned short*)pWlD,
        b_down, nullptr);

    dim3 g2(C_OUT / 128, M_UP / 128);   // (4, 512)
    gemm_bf16<C_UP, true><<<g2, 512, 4 * SM_STAGE>>>(
        (const unsigned short*)pAhU, (const unsigned short*)pAlU,
        (const unsigned short*)pWhU, (const unsigned short*)pWlU,
        b_up, out);
}

// round 9
// speedup vs baseline: 1.5733x; 1.5733x over previous
#include <cuda_runtime.h>
#include <math_constants.h>
#include <cstdint>

#define BATCH   4
#define N_UP    16384
#define N_DOWN  4096
#define C_UP    384
#define C_DOWN  512
#define C_OUT   512
#define KNN     3
#define EPSW    1e-8f

#define M_UP   (BATCH * N_UP)     // 65536
#define M_DN   (BATCH * N_DOWN)   // 16384

// ---------------- scratch (__device__ globals; no allocs allowed) ----------
__device__ float g_down_f[M_DN * C_OUT];                 // 32 MB fp32
__device__ int   g_idx[M_UP * KNN];
__device__ float g_w[M_UP * KNN];

__device__ unsigned short g_Ah_up[(size_t)M_UP * C_UP];  // fp16 hi of up_features
__device__ unsigned short g_Al_up[(size_t)M_UP * C_UP];  // fp16 lo
__device__ unsigned short g_W_up16[(size_t)C_OUT * C_UP];   // fp16 W_up
__device__ unsigned short g_Ah_dn[(size_t)M_DN * C_DOWN];
__device__ unsigned short g_Al_dn[(size_t)M_DN * C_DOWN];
__device__ unsigned short g_W_dn16[(size_t)C_OUT * C_DOWN];

// ---------------- helpers ---------------------------------------------------
static __device__ __forceinline__ uint32_t smem_u32(const void* p) {
    uint32_t a;
    asm("{ .reg .u64 t; cvta.to.shared.u64 t, %1; cvt.u32.u64 %0, t; }"
        : "=r"(a) : "l"(p));
    return a;
}
static __device__ __forceinline__ unsigned short f2h(float f) {
    unsigned short u;
    asm("cvt.rn.f16.f32 %0, %1;" : "=h"(u) : "f"(f));
    return u;
}
static __device__ __forceinline__ float h2f(unsigned short u) {
    float f;
    asm("cvt.f32.f16 %0, %1;" : "=f"(f) : "h"(u));
    return f;
}
static __device__ __forceinline__ void cp16(uint32_t dst, const void* src) {
    asm volatile("cp.async.cg.shared.global [%0], [%1], 16;"
                 :: "r"(dst), "l"(src) : "memory");
}
static __device__ __forceinline__ void cp_commit() {
    asm volatile("cp.async.commit_group;" ::: "memory");
}
static __device__ __forceinline__ void cp_wait2() {
    asm volatile("cp.async.wait_group 2;" ::: "memory");
}
static __device__ __forceinline__ void ldmx4(uint32_t& r0, uint32_t& r1,
                                             uint32_t& r2, uint32_t& r3,
                                             uint32_t addr) {
    asm volatile("ldmatrix.sync.aligned.m8n8.x4.shared.b16 {%0,%1,%2,%3}, [%4];"
                 : "=r"(r0), "=r"(r1), "=r"(r2), "=r"(r3) : "r"(addr));
}
static __device__ __forceinline__ void mma16816(float* c, const uint32_t* a,
                                                uint32_t b0, uint32_t b1) {
    asm volatile(
        "mma.sync.aligned.m16n8k16.row.col.f32.f16.f16.f32 "
        "{%0,%1,%2,%3}, {%4,%5,%6,%7}, {%8,%9}, {%0,%1,%2,%3};"
        : "+f"(c[0]), "+f"(c[1]), "+f"(c[2]), "+f"(c[3])
        : "r"(a[0]), "r"(a[1]), "r"(a[2]), "r"(a[3]), "r"(b0), "r"(b1));
}

// ---------------- fp16 conversions -----------------------------------------
__global__ __launch_bounds__(256) void conv_hilo16(
    const float4* __restrict__ x, ushort4* __restrict__ h4,
    ushort4* __restrict__ l4, int n4)
{
    int i = blockIdx.x * 256 + threadIdx.x;
    if (i >= n4) return;
    float4 v = x[i];
    ushort4 h, l;
    h.x = f2h(v.x); l.x = f2h(v.x - h2f(h.x));
    h.y = f2h(v.y); l.y = f2h(v.y - h2f(h.y));
    h.z = f2h(v.z); l.z = f2h(v.z - h2f(h.z));
    h.w = f2h(v.w); l.w = f2h(v.w - h2f(h.w));
    h4[i] = h; l4[i] = l;
}
__global__ __launch_bounds__(256) void conv_f16(
    const float4* __restrict__ x, ushort4* __restrict__ h4, int n4)
{
    int i = blockIdx.x * 256 + threadIdx.x;
    if (i >= n4) return;
    float4 v = x[i];
    h4[i] = make_ushort4(f2h(v.x), f2h(v.y), f2h(v.z), f2h(v.w));
}

// ---------------------------------------------------------------------------
// fp16 A-hi/lo GEMM via mma.sync: out[m,n] = sum_k A[m,k]*Wt[n,k] + bias[n]
// (+ KNN interpolation when FUSED). Effective K' = 2K via segments:
//   seg0: Ah*B   seg1: Al*B   (B single fp16; err ~1.6e-4 << tolerance)
// CTA 128x128, BK=32 fp16, 4-stage cp.async ring, 8 warps, warp tile 64x32.
// ---------------------------------------------------------------------------
#define SM_STAGE 20480            // (128 rows * 80B) * 2 (A+B)
template<int K, bool FUSED>
__global__ __launch_bounds__(256) void gemm_f16(
    const unsigned short* __restrict__ Ah, const unsigned short* __restrict__ Al,
    const unsigned short* __restrict__ Bf,
    const float* __restrict__ bias, float* __restrict__ outp)
{
    constexpr int SEGC = K / 32;
    constexpr int NC = 2 * SEGC;
    extern __shared__ __align__(16) char smt[];
    const uint32_t sbase = smem_u32(smt);

    const int tid = threadIdx.x;
    const int lane = tid & 31;
    const int wid = tid >> 5;
    const int wm = wid >> 2;        // 0..1 -> m offset wm*64
    const int wn = wid & 3;         // 0..3 -> n offset wn*32
    const int m0 = blockIdx.y * 128;
    const int n0 = blockIdx.x * 128;

    // cp.async slots: thread covers rows (row, row+64), 16B chunk q
    const int row = tid >> 2;
    const int q = tid & 3;

    // ldmatrix per-lane offsets
    const int lq = lane >> 3, l7 = lane & 7;
    const int aRow = (lq & 1) * 8 + l7, aK = (lq >> 1) * 8;
    const int bRow = (lq >> 1) * 8 + l7, bK = (lq & 1) * 8;

    float acc[4][4][4];
#pragma unroll
    for (int i = 0; i < 4; i++)
#pragma unroll
        for (int j = 0; j < 4; j++)
#pragma unroll
            for (int r = 0; r < 4; r++) acc[i][j][r] = 0.0f;

    auto issue = [&](int c) {
        if (c < NC) {
            const int seg = c / SEGC;
            const int kk = (c - seg * SEGC) * 32;
            const unsigned short* As = (seg == 0) ? Ah : Al;
            const unsigned short* srcA = As + (size_t)(m0 + row) * K + kk + q * 8;
            const unsigned short* srcB = Bf + (size_t)(n0 + row) * K + kk + q * 8;
            uint32_t dA = sbase + (c & 3) * SM_STAGE + row * 80 + q * 16;
            uint32_t dB = dA + 10240;
            cp16(dA, srcA);
            cp16(dA + 64 * 80, srcA + (size_t)64 * K);
            cp16(dB, srcB);
            cp16(dB + 64 * 80, srcB + (size_t)64 * K);
        }
        cp_commit();
    };

    issue(0); issue(1); issue(2);

    for (int c = 0; c < NC; c++) {
        cp_wait2();
        __syncthreads();
        issue(c + 3);                 // overwrites stage (c-1)&3: safe past sync

        const uint32_t sA = sbase + (c & 3) * SM_STAGE;
        const uint32_t sB = sA + 10240;
#pragma unroll
        for (int ks = 0; ks < 2; ks++) {
            uint32_t a[4][4];
#pragma unroll
            for (int i = 0; i < 4; i++) {
                uint32_t addr = sA + (uint32_t)(wm * 64 + i * 16 + aRow) * 80
                              + (uint32_t)(ks * 16 + aK) * 2;
                ldmx4(a[i][0], a[i][1], a[i][2], a[i][3], addr);
            }
            uint32_t b[4][2];
#pragma unroll
            for (int jp = 0; jp < 2; jp++) {
                uint32_t addr = sB + (uint32_t)(wn * 32 + jp * 16 + bRow) * 80
                              + (uint32_t)(ks * 16 + bK) * 2;
                ldmx4(b[jp * 2][0], b[jp * 2][1], b[jp * 2 + 1][0], b[jp * 2 + 1][1], addr);
            }
#pragma unroll
            for (int i = 0; i < 4; i++)
#pragma unroll
                for (int j = 0; j < 4; j++)
                    mma16816(acc[i][j], a[i], b[j][0], b[j][1]);
        }
    }

    // ---------------- epilogue ----------------
    float* obase = FUSED ? outp : g_down_f;
#pragma unroll
    for (int i = 0; i < 4; i++) {
        const int r0 = m0 + wm * 64 + i * 16 + (lane >> 2);
        const int r1 = r0 + 8;
        const float* df0 = nullptr; const float* df1 = nullptr;
        int i00=0,i01=0,i02=0, i10=0,i11=0,i12=0;
        float w00=0,w01=0,w02=0, w10=0,w11=0,w12=0;
        if (FUSED) {
            df0 = g_down_f + (size_t)(r0 >> 14) * N_DOWN * C_OUT;
            df1 = g_down_f + (size_t)(r1 >> 14) * N_DOWN * C_OUT;
            int ib0 = r0 * KNN, ib1 = r1 * KNN;
            i00 = g_idx[ib0]; i01 = g_idx[ib0+1]; i02 = g_idx[ib0+2];
            w00 = g_w[ib0];   w01 = g_w[ib0+1];   w02 = g_w[ib0+2];
            i10 = g_idx[ib1]; i11 = g_idx[ib1+1]; i12 = g_idx[ib1+2];
            w10 = g_w[ib1];   w11 = g_w[ib1+1];   w12 = g_w[ib1+2];
        }
#pragma unroll
        for (int j = 0; j < 4; j++) {
            const int n = n0 + wn * 32 + j * 8 + (lane & 3) * 2;
            const float2 bi = *(const float2*)(bias + n);
            float2 o0, o1;
            o0.x = acc[i][j][0] + bi.x;  o0.y = acc[i][j][1] + bi.y;
            o1.x = acc[i][j][2] + bi.x;  o1.y = acc[i][j][3] + bi.y;
            if (FUSED) {
                float2 a0 = *(const float2*)(df0 + (size_t)i00 * C_OUT + n);
                float2 a1 = *(const float2*)(df0 + (size_t)i01 * C_OUT + n);
                float2 a2 = *(const float2*)(df0 + (size_t)i02 * C_OUT + n);
                o0.x += w00 * a0.x + w01 * a1.x + w02 * a2.x;
                o0.y += w00 * a0.y + w01 * a1.y + w02 * a2.y;
                float2 c0 = *(const float2*)(df1 + (size_t)i10 * C_OUT + n);
                float2 c1 = *(const float2*)(df1 + (size_t)i11 * C_OUT + n);
                float2 c2 = *(const float2*)(df1 + (size_t)i12 * C_OUT + n);
                o1.x += w10 * c0.x + w11 * c1.x + w12 * c2.x;
                o1.y += w10 * c0.y + w11 * c1.y + w12 * c2.y;
            }
            *(float2*)(obase + (size_t)r0 * C_OUT + n) = o0;
            *(float2*)(obase + (size_t)r1 * C_OUT + n) = o1;
        }
    }
}

// ---------------------------------------------------------------------------
// KNN: rank by t = d2 - 2*dot; strict-< insertion for stability.
// ---------------------------------------------------------------------------
__global__ __launch_bounds__(256) void knn_kernel(
    const float* __restrict__ up_points,
    const float* __restrict__ down_points)
{
    __shared__ float4 sp[2048];

    const int b = blockIdx.y;
    const int n = blockIdx.x * 256 + threadIdx.x;

    const float* up = up_points + (size_t)(b * N_UP + n) * 3;
    const float ux = up[0], uy = up[1], uz = up[2];
    const float u2 = ux * ux + uy * uy + uz * uz;
    const float a0 = -2.0f * ux, a1 = -2.0f * uy, a2 = -2.0f * uz;

    float bd0 = CUDART_INF_F, bd1 = CUDART_INF_F, bd2 = CUDART_INF_F;
    int   bi0 = 0, bi1 = 0, bi2 = 0;

    for (int phase = 0; phase < 2; phase++) {
        const int mbase = phase * 2048;
        __syncthreads();
        for (int i = threadIdx.x; i < 2048; i += 256) {
            const float* dp = down_points + (size_t)(b * N_DOWN + mbase + i) * 3;
            float x = dp[0], y = dp[1], z = dp[2];
            sp[i] = make_float4(x, y, z, x * x + y * y + z * z);
        }
        __syncthreads();

        for (int m = 0; m < 2048; m += 8) {
            float t[8];
#pragma unroll
            for (int j = 0; j < 8; j++) {
                float4 p = sp[m + j];
                t[j] = fmaf(a0, p.x, fmaf(a1, p.y, fmaf(a2, p.z, p.w)));
            }
            float mn = fminf(fminf(fminf(t[0], t[1]), fminf(t[2], t[3])),
                             fminf(fminf(t[4], t[5]), fminf(t[6], t[7])));
            if (mn < bd2) {
#pragma unroll
                for (int j = 0; j < 8; j++) {
                    float d = t[j];
                    if (d < bd2) {
                        int mi = mbase + m + j;
                        if (d < bd1) {
                            bd2 = bd1; bi2 = bi1;
                            if (d < bd0) { bd1 = bd0; bi1 = bi0; bd0 = d; bi0 = mi; }
                            else          { bd1 = d;  bi1 = mi; }
                        } else {
                            bd2 = d; bi2 = mi;
                        }
                    }
                }
            }
        }
    }

    float d0 = bd0 + u2, d1 = bd1 + u2, d2 = bd2 + u2;
    float w0 = 1.0f / (d0 + EPSW);
    float w1 = 1.0f / (d1 + EPSW);
    float w2 = 1.0f / (d2 + EPSW);
    float inv = 1.0f / (w0 + w1 + w2);

    const int base = (b * N_UP + n) * KNN;
    g_idx[base + 0] = bi0; g_idx[base + 1] = bi1; g_idx[base + 2] = bi2;
    g_w[base + 0] = w0 * inv; g_w[base + 1] = w1 * inv; g_w[base + 2] = w2 * inv;
}

// ---------------------------------------------------------------------------
extern "C" void kernel_launch(void* const* d_in, const int* in_sizes, int n_in,
                              void* d_out, int out_size) {
    (void)in_sizes; (void)n_in; (void)out_size;
    const float* up_points     = (const float*)d_in[0];
    const float* up_features   = (const float*)d_in[1];
    const float* down_points   = (const float*)d_in[2];
    const float* down_features = (const float*)d_in[3];
    const float* W_up          = (const float*)d_in[4];
    const float* b_up          = (const float*)d_in[5];
    const float* W_down        = (const float*)d_in[6];
    const float* b_down        = (const float*)d_in[7];
    float* out = (float*)d_out;

    void *pAhU, *pAlU, *pWU, *pAhD, *pAlD, *pWD;
    cudaGetSymbolAddress(&pAhU, g_Ah_up);
    cudaGetSymbolAddress(&pAlU, g_Al_up);
    cudaGetSymbolAddress(&pWU,  g_W_up16);
    cudaGetSymbolAddress(&pAhD, g_Ah_dn);
    cudaGetSymbolAddress(&pAlD, g_Al_dn);
    cudaGetSymbolAddress(&pWD,  g_W_dn16);

    cudaFuncSetAttribute(gemm_f16<C_DOWN, false>,
                         cudaFuncAttributeMaxDynamicSharedMemorySize, 4 * SM_STAGE);
    cudaFuncSetAttribute(gemm_f16<C_UP, true>,
                         cudaFuncAttributeMaxDynamicSharedMemorySize, 4 * SM_STAGE);

    // conversions
    {
        int n4 = M_UP * C_UP / 4;
        conv_hilo16<<<(n4 + 255) / 256, 256>>>((const float4*)up_features,
                                               (ushort4*)pAhU, (ushort4*)pAlU, n4);
    }
    {
        int n4 = C_OUT * C_UP / 4;
        conv_f16<<<(n4 + 255) / 256, 256>>>((const float4*)W_up, (ushort4*)pWU, n4);
    }
    {
        int n4 = M_DN * C_DOWN / 4;
        conv_hilo16<<<(n4 + 255) / 256, 256>>>((const float4*)down_features,
                                               (ushort4*)pAhD, (ushort4*)pAlD, n4);
    }
    {
        int n4 = C_OUT * C_DOWN / 4;
        conv_f16<<<(n4 + 255) / 256, 256>>>((const float4*)W_down, (ushort4*)pWD, n4);
    }

    dim3 gk(N_UP / 256, BATCH);
    knn_kernel<<<gk, 256>>>(up_points, down_points);

    dim3 g1(C_OUT / 128, M_DN / 128);   // (4, 128)
    gemm_f16<C_DOWN, false><<<g1, 256, 4 * SM_STAGE>>>(
        (const unsigned short*)pAhD, (const unsigned short*)pAlD,
        (const unsigned short*)pWD, b_down, nullptr);

    dim3 g2(C_OUT / 128, M_UP / 128);   // (4, 512)
    gemm_f16<C_UP, true><<<g2, 256, 4 * SM_STAGE>>>(
        (const unsigned short*)pAhU, (const unsigned short*)pAlU,
        (const unsigned short*)pWU, b_up, out);
}

// round 10
// speedup vs baseline: 2.0437x; 1.2990x over previous
#include <cuda_runtime.h>
#include <math_constants.h>
#include <cstdint>

#define BATCH   4
#define N_UP    16384
#define N_DOWN  4096
#define C_UP    384
#define C_DOWN  512
#define C_OUT   512
#define KNN     3
#define EPSW    1e-8f

#define M_UP   (BATCH * N_UP)     // 65536
#define M_DN   (BATCH * N_DOWN)   // 16384

// ---------------- scratch (__device__ globals; no allocs allowed) ----------
__device__ float g_down_f[M_DN * C_OUT];                 // 32 MB fp32
__device__ int   g_idx[M_UP * KNN];
__device__ float g_w[M_UP * KNN];

__device__ unsigned short g_A_up[(size_t)M_UP * C_UP];      // fp16 up_features
__device__ unsigned short g_W_up16[(size_t)C_OUT * C_UP];   // fp16 W_up
__device__ unsigned short g_A_dn[(size_t)M_DN * C_DOWN];    // fp16 down_features
__device__ unsigned short g_W_dn16[(size_t)C_OUT * C_DOWN]; // fp16 W_down

// ---------------- helpers ---------------------------------------------------
static __device__ __forceinline__ uint32_t smem_u32(const void* p) {
    uint32_t a;
    asm("{ .reg .u64 t; cvta.to.shared.u64 t, %1; cvt.u32.u64 %0, t; }"
        : "=r"(a) : "l"(p));
    return a;
}
static __device__ __forceinline__ unsigned short f2h(float f) {
    unsigned short u;
    asm("cvt.rn.f16.f32 %0, %1;" : "=h"(u) : "f"(f));
    return u;
}
static __device__ __forceinline__ void cp16(uint32_t dst, const void* src) {
    asm volatile("cp.async.cg.shared.global [%0], [%1], 16;"
                 :: "r"(dst), "l"(src) : "memory");
}
static __device__ __forceinline__ void cp_commit() {
    asm volatile("cp.async.commit_group;" ::: "memory");
}
static __device__ __forceinline__ void cp_wait2() {
    asm volatile("cp.async.wait_group 2;" ::: "memory");
}
static __device__ __forceinline__ void ldmx4(uint32_t& r0, uint32_t& r1,
                                             uint32_t& r2, uint32_t& r3,
                                             uint32_t addr) {
    asm volatile("ldmatrix.sync.aligned.m8n8.x4.shared.b16 {%0,%1,%2,%3}, [%4];"
                 : "=r"(r0), "=r"(r1), "=r"(r2), "=r"(r3) : "r"(addr));
}
static __device__ __forceinline__ void mma16816(float* c, const uint32_t* a,
                                                uint32_t b0, uint32_t b1) {
    asm volatile(
        "mma.sync.aligned.m16n8k16.row.col.f32.f16.f16.f32 "
        "{%0,%1,%2,%3}, {%4,%5,%6,%7}, {%8,%9}, {%0,%1,%2,%3};"
        : "+f"(c[0]), "+f"(c[1]), "+f"(c[2]), "+f"(c[3])
        : "r"(a[0]), "r"(a[1]), "r"(a[2]), "r"(a[3]), "r"(b0), "r"(b1));
}

// ---------------- fp16 conversion -------------------------------------------
__global__ __launch_bounds__(256) void conv_f16(
    const float4* __restrict__ x, ushort4* __restrict__ h4, int n4)
{
    int i = blockIdx.x * 256 + threadIdx.x;
    if (i >= n4) return;
    float4 v = x[i];
    h4[i] = make_ushort4(f2h(v.x), f2h(v.y), f2h(v.z), f2h(v.w));
}

// ---------------------------------------------------------------------------
// fp16 GEMM via mma.sync: out[m,n] = sum_k A[m,k]*Wt[n,k] + bias[n]
// (+ KNN interpolation when FUSED). Single fp16 segment (A and B both rn-
// rounded; measured per-side quadrature cost ~2.1e-4, total stays < 1e-3).
// CTA 128x128, BK=32 fp16, 4-stage cp.async ring, 8 warps, warp tile 64x32.
// ---------------------------------------------------------------------------
#define SM_STAGE 20480            // (128 rows * 80B) * 2 (A+B)
template<int K, bool FUSED>
__global__ __launch_bounds__(256) void gemm_f16(
    const unsigned short* __restrict__ Af,
    const unsigned short* __restrict__ Bf,
    const float* __restrict__ bias, float* __restrict__ outp)
{
    constexpr int NC = K / 32;
    extern __shared__ __align__(16) char smt[];
    const uint32_t sbase = smem_u32(smt);

    const int tid = threadIdx.x;
    const int lane = tid & 31;
    const int wid = tid >> 5;
    const int wm = wid >> 2;        // 0..1 -> m offset wm*64
    const int wn = wid & 3;         // 0..3 -> n offset wn*32
    const int m0 = blockIdx.y * 128;
    const int n0 = blockIdx.x * 128;

    // cp.async slots: thread covers rows (row, row+64), 16B chunk q
    const int row = tid >> 2;
    const int q = tid & 3;

    // ldmatrix per-lane offsets
    const int lq = lane >> 3, l7 = lane & 7;
    const int aRow = (lq & 1) * 8 + l7, aK = (lq >> 1) * 8;
    const int bRow = (lq >> 1) * 8 + l7, bK = (lq & 1) * 8;

    float acc[4][4][4];
#pragma unroll
    for (int i = 0; i < 4; i++)
#pragma unroll
        for (int j = 0; j < 4; j++)
#pragma unroll
            for (int r = 0; r < 4; r++) acc[i][j][r] = 0.0f;

    auto issue = [&](int c) {
        if (c < NC) {
            const int kk = c * 32;
            const unsigned short* srcA = Af + (size_t)(m0 + row) * K + kk + q * 8;
            const unsigned short* srcB = Bf + (size_t)(n0 + row) * K + kk + q * 8;
            uint32_t dA = sbase + (c & 3) * SM_STAGE + row * 80 + q * 16;
            uint32_t dB = dA + 10240;
            cp16(dA, srcA);
            cp16(dA + 64 * 80, srcA + (size_t)64 * K);
            cp16(dB, srcB);
            cp16(dB + 64 * 80, srcB + (size_t)64 * K);
        }
        cp_commit();
    };

    issue(0); issue(1); issue(2);

    for (int c = 0; c < NC; c++) {
        cp_wait2();
        __syncthreads();
        issue(c + 3);                 // overwrites stage (c-1)&3: safe past sync

        const uint32_t sA = sbase + (c & 3) * SM_STAGE;
        const uint32_t sB = sA + 10240;
#pragma unroll
        for (int ks = 0; ks < 2; ks++) {
            uint32_t a[4][4];
#pragma unroll
            for (int i = 0; i < 4; i++) {
                uint32_t addr = sA + (uint32_t)(wm * 64 + i * 16 + aRow) * 80
                              + (uint32_t)(ks * 16 + aK) * 2;
                ldmx4(a[i][0], a[i][1], a[i][2], a[i][3], addr);
            }
            uint32_t b[4][2];
#pragma unroll
            for (int jp = 0; jp < 2; jp++) {
                uint32_t addr = sB + (uint32_t)(wn * 32 + jp * 16 + bRow) * 80
                              + (uint32_t)(ks * 16 + bK) * 2;
                ldmx4(b[jp * 2][0], b[jp * 2][1], b[jp * 2 + 1][0], b[jp * 2 + 1][1], addr);
            }
#pragma unroll
            for (int i = 0; i < 4; i++)
#pragma unroll
                for (int j = 0; j < 4; j++)
                    mma16816(acc[i][j], a[i], b[j][0], b[j][1]);
        }
    }

    // ---------------- epilogue ----------------
    float* obase = FUSED ? outp : g_down_f;
#pragma unroll
    for (int i = 0; i < 4; i++) {
        const int r0 = m0 + wm * 64 + i * 16 + (lane >> 2);
        const int r1 = r0 + 8;
        const float* df0 = nullptr; const float* df1 = nullptr;
        int i00=0,i01=0,i02=0, i10=0,i11=0,i12=0;
        float w00=0,w01=0,w02=0, w10=0,w11=0,w12=0;
        if (FUSED) {
            df0 = g_down_f + (size_t)(r0 >> 14) * N_DOWN * C_OUT;
            df1 = g_down_f + (size_t)(r1 >> 14) * N_DOWN * C_OUT;
            int ib0 = r0 * KNN, ib1 = r1 * KNN;
            i00 = g_idx[ib0]; i01 = g_idx[ib0+1]; i02 = g_idx[ib0+2];
            w00 = g_w[ib0];   w01 = g_w[ib0+1];   w02 = g_w[ib0+2];
            i10 = g_idx[ib1]; i11 = g_idx[ib1+1]; i12 = g_idx[ib1+2];
            w10 = g_w[ib1];   w11 = g_w[ib1+1];   w12 = g_w[ib1+2];
        }
#pragma unroll
        for (int j = 0; j < 4; j++) {
            const int n = n0 + wn * 32 + j * 8 + (lane & 3) * 2;
            const float2 bi = *(const float2*)(bias + n);
            float2 o0, o1;
            o0.x = acc[i][j][0] + bi.x;  o0.y = acc[i][j][1] + bi.y;
            o1.x = acc[i][j][2] + bi.x;  o1.y = acc[i][j][3] + bi.y;
            if (FUSED) {
                float2 a0 = *(const float2*)(df0 + (size_t)i00 * C_OUT + n);
                float2 a1 = *(const float2*)(df0 + (size_t)i01 * C_OUT + n);
                float2 a2 = *(const float2*)(df0 + (size_t)i02 * C_OUT + n);
                o0.x += w00 * a0.x + w01 * a1.x + w02 * a2.x;
                o0.y += w00 * a0.y + w01 * a1.y + w02 * a2.y;
                float2 c0 = *(const float2*)(df1 + (size_t)i10 * C_OUT + n);
                float2 c1 = *(const float2*)(df1 + (size_t)i11 * C_OUT + n);
                float2 c2 = *(const float2*)(df1 + (size_t)i12 * C_OUT + n);
                o1.x += w10 * c0.x + w11 * c1.x + w12 * c2.x;
                o1.y += w10 * c0.y + w11 * c1.y + w12 * c2.y;
            }
            *(float2*)(obase + (size_t)r0 * C_OUT + n) = o0;
            *(float2*)(obase + (size_t)r1 * C_OUT + n) = o1;
        }
    }
}

// ---------------------------------------------------------------------------
// KNN: rank by t = d2 - 2*dot; strict-< insertion for stability.
// ---------------------------------------------------------------------------
__global__ __launch_bounds__(256) void knn_kernel(
    const float* __restrict__ up_points,
    const float* __restrict__ down_points)
{
    __shared__ float4 sp[2048];

    const int b = blockIdx.y;
    const int n = blockIdx.x * 256 + threadIdx.x;

    const float* up = up_points + (size_t)(b * N_UP + n) * 3;
    const float ux = up[0], uy = up[1], uz = up[2];
    const float u2 = ux * ux + uy * uy + uz * uz;
    const float a0 = -2.0f * ux, a1 = -2.0f * uy, a2 = -2.0f * uz;

    float bd0 = CUDART_INF_F, bd1 = CUDART_INF_F, bd2 = CUDART_INF_F;
    int   bi0 = 0, bi1 = 0, bi2 = 0;

    for (int phase = 0; phase < 2; phase++) {
        const int mbase = phase * 2048;
        __syncthreads();
        for (int i = threadIdx.x; i < 2048; i += 256) {
            const float* dp = down_points + (size_t)(b * N_DOWN + mbase + i) * 3;
            float x = dp[0], y = dp[1], z = dp[2];
            sp[i] = make_float4(x, y, z, x * x + y * y + z * z);
        }
        __syncthreads();

        for (int m = 0; m < 2048; m += 8) {
            float t[8];
#pragma unroll
            for (int j = 0; j < 8; j++) {
                float4 p = sp[m + j];
                t[j] = fmaf(a0, p.x, fmaf(a1, p.y, fmaf(a2, p.z, p.w)));
            }
            float mn = fminf(fminf(fminf(t[0], t[1]), fminf(t[2], t[3])),
                             fminf(fminf(t[4], t[5]), fminf(t[6], t[7])));
            if (mn < bd2) {
#pragma unroll
                for (int j = 0; j < 8; j++) {
                    float d = t[j];
                    if (d < bd2) {
                        int mi = mbase + m + j;
                        if (d < bd1) {
                            bd2 = bd1; bi2 = bi1;
                            if (d < bd0) { bd1 = bd0; bi1 = bi0; bd0 = d; bi0 = mi; }
                            else          { bd1 = d;  bi1 = mi; }
                        } else {
                            bd2 = d; bi2 = mi;
                        }
                    }
                }
            }
        }
    }

    float d0 = bd0 + u2, d1 = bd1 + u2, d2 = bd2 + u2;
    float w0 = 1.0f / (d0 + EPSW);
    float w1 = 1.0f / (d1 + EPSW);
    float w2 = 1.0f / (d2 + EPSW);
    float inv = 1.0f / (w0 + w1 + w2);

    const int base = (b * N_UP + n) * KNN;
    g_idx[base + 0] = bi0; g_idx[base + 1] = bi1; g_idx[base + 2] = bi2;
    g_w[base + 0] = w0 * inv; g_w[base + 1] = w1 * inv; g_w[base + 2] = w2 * inv;
}

// ---------------------------------------------------------------------------
extern "C" void kernel_launch(void* const* d_in, const int* in_sizes, int n_in,
                              void* d_out, int out_size) {
    (void)in_sizes; (void)n_in; (void)out_size;
    const float* up_points     = (const float*)d_in[0];
    const float* up_features   = (const float*)d_in[1];
    const float* down_points   = (const float*)d_in[2];
    const float* down_features = (const float*)d_in[3];
    const float* W_up          = (const float*)d_in[4];
    const float* b_up          = (const float*)d_in[5];
    const float* W_down        = (const float*)d_in[6];
    const float* b_down        = (const float*)d_in[7];
    float* out = (float*)d_out;

    void *pAU, *pWU, *pAD, *pWD;
    cudaGetSymbolAddress(&pAU, g_A_up);
    cudaGetSymbolAddress(&pWU, g_W_up16);
    cudaGetSymbolAddress(&pAD, g_A_dn);
    cudaGetSymbolAddress(&pWD, g_W_dn16);

    cudaFuncSetAttribute(gemm_f16<C_DOWN, false>,
                         cudaFuncAttributeMaxDynamicSharedMemorySize, 4 * SM_STAGE);
    cudaFuncSetAttribute(gemm_f16<C_UP, true>,
                         cudaFuncAttributeMaxDynamicSharedMemorySize, 4 * SM_STAGE);

    // conversions
    {
        int n4 = M_UP * C_UP / 4;
        conv_f16<<<(n4 + 255) / 256, 256>>>((const float4*)up_features,
                                            (ushort4*)pAU, n4);
    }
    {
        int n4 = C_OUT * C_UP / 4;
        conv_f16<<<(n4 + 255) / 256, 256>>>((const float4*)W_up, (ushort4*)pWU, n4);
    }
    {
        int n4 = M_DN * C_DOWN / 4;
        conv_f16<<<(n4 + 255) / 256, 256>>>((const float4*)down_features,
                                            (ushort4*)pAD, n4);
    }
    {
        int n4 = C_OUT * C_DOWN / 4;
        conv_f16<<<(n4 + 255) / 256, 256>>>((const float4*)W_down, (ushort4*)pWD, n4);
    }

    dim3 gk(N_UP / 256, BATCH);
    knn_kernel<<<gk, 256>>>(up_points, down_points);

    dim3 g1(C_OUT / 128, M_DN / 128);   // (4, 128)
    gemm_f16<C_DOWN, false><<<g1, 256, 4 * SM_STAGE>>>(
        (const unsigned short*)pAD, (const unsigned short*)pWD, b_down, nullptr);

    dim3 g2(C_OUT / 128, M_UP / 128);   // (4, 512)
    gemm_f16<C_UP, true><<<g2, 256, 4 * SM_STAGE>>>(
        (const unsigned short*)pAU, (const unsigned short*)pWU, b_up, out);
}